// round 16
// baseline (speedup 1.0000x reference)
#include <cuda_runtime.h>
#include <cuda_bf16.h>
#include <math.h>
#include <stdint.h>

#define DMODEL 1024
#define NHEAD  16
#define HD     64
#define NB     4
#define SQ     1024
#define SK     2048

// ---------------------------------------------------------------------------
// Scratch (__device__ globals)
// ---------------------------------------------------------------------------
// tf32-rounded fp32 GEMM operands
__device__ float g_qr[NB * SQ * DMODEL];
__device__ float g_kvr[NB * SK * DMODEL];
__device__ float g_wqr[DMODEL * DMODEL];
__device__ float g_wkr[DMODEL * DMODEL];
__device__ float g_wvr[DMODEL * DMODEL];
// O-projection operands (bf16 3-term kept for accuracy)
__device__ __nv_bfloat16 g_woh[DMODEL * DMODEL];
__device__ __nv_bfloat16 g_wol[DMODEL * DMODEL];
__device__ __nv_bfloat16 g_oh[NB * SQ * DMODEL];
__device__ __nv_bfloat16 g_ol[NB * SQ * DMODEL];
// attention operands: Q/K post-RoPE tf32 fp32; V bf16 hi/lo
__device__ float g_aq[NB * SQ * DMODEL];
__device__ float g_ak[NB * SK * DMODEL];
__device__ __nv_bfloat16 g_avh[NB * SK * DMODEL];
__device__ __nv_bfloat16 g_avl[NB * SK * DMODEL];

// ---------------------------------------------------------------------------
// Helpers
// ---------------------------------------------------------------------------
__device__ __forceinline__ uint32_t smem_u32(const void* p) {
    uint32_t a;
    asm("{ .reg .u64 t; cvta.to.shared.u64 t, %1; cvt.u32.u64 %0, t; }" : "=r"(a) : "l"(p));
    return a;
}
__device__ __forceinline__ void cp16(uint32_t dst, const void* src) {
    asm volatile("cp.async.cg.shared.global [%0], [%1], 16;" :: "r"(dst), "l"(src));
}
__device__ __forceinline__ void cp_commit() {
    asm volatile("cp.async.commit_group;" ::: "memory");
}
__device__ __forceinline__ void cp_wait1() {
    asm volatile("cp.async.wait_group 1;" ::: "memory");
}
__device__ __forceinline__ void cp_wait0() {
    asm volatile("cp.async.wait_group 0;" ::: "memory");
}
__device__ __forceinline__ void ldsm_x4(uint32_t addr, uint32_t* r) {
    asm volatile("ldmatrix.sync.aligned.m8n8.x4.shared.b16 {%0,%1,%2,%3}, [%4];"
                 : "=r"(r[0]), "=r"(r[1]), "=r"(r[2]), "=r"(r[3]) : "r"(addr));
}
__device__ __forceinline__ void ldsm_x4t(uint32_t addr, uint32_t* r) {
    asm volatile("ldmatrix.sync.aligned.m8n8.x4.trans.shared.b16 {%0,%1,%2,%3}, [%4];"
                 : "=r"(r[0]), "=r"(r[1]), "=r"(r[2]), "=r"(r[3]) : "r"(addr));
}
__device__ __forceinline__ void mma_bf16(float* d, const uint32_t* a, uint32_t b0, uint32_t b1) {
    asm volatile(
        "mma.sync.aligned.m16n8k16.row.col.f32.bf16.bf16.f32 "
        "{%0,%1,%2,%3}, {%4,%5,%6,%7}, {%8,%9}, {%0,%1,%2,%3};"
        : "+f"(d[0]), "+f"(d[1]), "+f"(d[2]), "+f"(d[3])
        : "r"(a[0]), "r"(a[1]), "r"(a[2]), "r"(a[3]), "r"(b0), "r"(b1));
}
__device__ __forceinline__ void mma_tf32(float* d, const uint32_t* a, uint32_t b0, uint32_t b1) {
    asm volatile(
        "mma.sync.aligned.m16n8k8.row.col.f32.tf32.tf32.f32 "
        "{%0,%1,%2,%3}, {%4,%5,%6,%7}, {%8,%9}, {%0,%1,%2,%3};"
        : "+f"(d[0]), "+f"(d[1]), "+f"(d[2]), "+f"(d[3])
        : "r"(a[0]), "r"(a[1]), "r"(a[2]), "r"(a[3]), "r"(b0), "r"(b1));
}
__device__ __forceinline__ uint32_t rna_tf32(float x) {
    uint32_t r;
    asm("cvt.rna.tf32.f32 %0, %1;" : "=r"(r) : "f"(x));
    return r;
}
// exp on the FMA pipe: 2^(x*log2e), deg-5 poly. rel err ~5e-7.
__device__ __forceinline__ float fast_exp(float x) {
    float y = fmaxf(x * 1.4426950408889634f, -100.0f);
    int n = __float2int_rn(y);
    float f = y - (float)n;
    float p = 1.3333558146e-3f;
    p = fmaf(p, f, 9.6181291076e-3f);
    p = fmaf(p, f, 5.5504108665e-2f);
    p = fmaf(p, f, 2.4022650696e-1f);
    p = fmaf(p, f, 6.9314718056e-1f);
    p = fmaf(p, f, 1.0f);
    return __int_as_float(__float_as_int(p) + (n << 23));
}
// split (a,b) fp32 pair -> bf16x2 hi + bf16x2 lo (lo = residual)
__device__ __forceinline__ void pack_split(float a, float b, uint32_t& hi2, uint32_t& lo2) {
    __nv_bfloat162 hb = __float22bfloat162_rn(make_float2(a, b));
    uint32_t h;
    memcpy(&h, &hb, 4);
    float ra = a - __uint_as_float(h << 16);
    float rb = b - __uint_as_float(h & 0xFFFF0000u);
    __nv_bfloat162 lb = __float22bfloat162_rn(make_float2(ra, rb));
    uint32_t l;
    memcpy(&l, &lb, 4);
    hi2 = h; lo2 = l;
}

// ---------------------------------------------------------------------------
// Pre-pass: segs (each 2^20): 0-2 q/k/v weights -> rna fp32; 3 out_w -> bf16
// split; 4-7 query -> rna; 8-15 kv -> rna.
// ---------------------------------------------------------------------------
#define NWE (DMODEL * DMODEL)

__global__ void round_all(const float* __restrict__ q_w, const float* __restrict__ k_w,
                          const float* __restrict__ v_w, const float* __restrict__ o_w,
                          const float* __restrict__ query, const float* __restrict__ kvp,
                          float* __restrict__ wqr, float* __restrict__ wkr,
                          float* __restrict__ wvr,
                          __nv_bfloat16* __restrict__ woh, __nv_bfloat16* __restrict__ wol,
                          float* __restrict__ qr, float* __restrict__ kvr)
{
    const long long i = (long long)(blockIdx.x * blockDim.x + threadIdx.x) * 4;
    const int seg = (int)(i >> 20);

    if (seg == 3) {
        const long long off = i & (NWE - 1);
        float4 v = *(const float4*)(o_w + off);
        uint32_t ha, la, hb, lb;
        pack_split(v.x, v.y, ha, la);
        pack_split(v.z, v.w, hb, lb);
        *(uint2*)(woh + off) = make_uint2(ha, hb);
        *(uint2*)(wol + off) = make_uint2(la, lb);
        return;
    }

    const float* src;
    float* dst;
    long long off;
    if (seg < 3) {
        off = i & (NWE - 1);
        src = (seg == 0) ? q_w : (seg == 1) ? k_w : v_w;
        dst = (seg == 0) ? wqr : (seg == 1) ? wkr : wvr;
    } else if (seg < 8) {
        off = i - 4LL * NWE;
        src = query; dst = qr;
    } else {
        off = i - 8LL * NWE;
        src = kvp; dst = kvr;
    }
    float4 v = *(const float4*)(src + off);
    float4 o;
    o.x = __uint_as_float(rna_tf32(v.x));
    o.y = __uint_as_float(rna_tf32(v.y));
    o.z = __uint_as_float(rna_tf32(v.z));
    o.w = __uint_as_float(rna_tf32(v.w));
    *(float4*)(dst + off) = o;
}

// ---------------------------------------------------------------------------
// tf32 merged Q/K/V projection GEMM (R15-validated mainloop). Grid (8, 160).
// Epilogues: Q/K -> RoPE + scale -> rna fp32 (for tf32 attention S);
//            V   -> bf16 hi/lo (PV stays bf16 3-term).
// ---------------------------------------------------------------------------
#define GEMM_SMEM 65536
#define NCH32 32

__global__ __launch_bounds__(256, 2)
void mma_gemm_qkv(const float* __restrict__ qr, const float* __restrict__ kvr,
                  const float* __restrict__ wqr, const float* __restrict__ wkr,
                  const float* __restrict__ wvr,
                  const float* __restrict__ q_b, const float* __restrict__ k_b,
                  const float* __restrict__ v_b,
                  float* __restrict__ aq, float* __restrict__ ak,
                  __nv_bfloat16* __restrict__ avh, __nv_bfloat16* __restrict__ avl)
{
    extern __shared__ char smc[];
    const uint32_t sbase = smem_u32(smc);
    const int tid = threadIdx.x;
    const int lane = tid & 31;
    const int wid = tid >> 5;
    const int warp_m = wid & 3;
    const int warp_n = wid >> 2;
    const int y = blockIdx.y;
    const int n0 = blockIdx.x * 128;

    const float *A, *W, *bias;
    float* Fo;
    int m0, L, posStride, doRope;
    float scale;
    if (y < 32) {
        A = qr; W = wqr; bias = q_b; Fo = aq; m0 = y * 128;
        L = SQ; posStride = 2; scale = 0.125f; doRope = 1;
    } else if (y < 96) {
        A = kvr; W = wkr; bias = k_b; Fo = ak; m0 = (y - 32) * 128;
        L = SK; posStride = 1; scale = 1.0f; doRope = 1;
    } else {
        A = kvr; W = wvr; bias = v_b; Fo = nullptr; m0 = (y - 96) * 128;
        L = 0; posStride = 0; scale = 0.f; doRope = 0;
    }

    const int lc = tid & 7;
    const int lr = tid >> 3;

    float acc[2][8][4];
#pragma unroll
    for (int mi = 0; mi < 2; mi++)
#pragma unroll
        for (int ni = 0; ni < 8; ni++)
#pragma unroll
            for (int e = 0; e < 4; e++) acc[mi][ni][e] = 0.f;

    auto issue_load = [&](int ci) {
        const int kk = ci * 32;
        const uint32_t st = (ci & 1) ? 32768u : 0u;
        const uint32_t da = sbase + st;
        const uint32_t db = sbase + st + 16384u;
        const uint32_t sw = ((uint32_t)(lc ^ (lr & 7))) << 4;
#pragma unroll
        for (int p = 0; p < 4; p++) {
            const int r = lr + p * 32;
            const uint32_t so = (uint32_t)(r * 128) + sw;
            cp16(da + so, A + (size_t)(m0 + r) * DMODEL + kk + lc * 4);
            cp16(db + so, W + (size_t)(n0 + r) * DMODEL + kk + lc * 4);
        }
    };

    issue_load(0);
    cp_commit();

    for (int i = 0; i < NCH32; i++) {
        if (i + 1 < NCH32) {
            issue_load(i + 1);
            cp_commit();
            cp_wait1();
        } else {
            cp_wait0();
        }
        __syncthreads();

        const uint32_t st = (i & 1) ? 32768u : 0u;
        const uint32_t abase = sbase + st + (uint32_t)(warp_m * 32) * 128;
        const uint32_t bbase = sbase + st + 16384u + (uint32_t)(warp_n * 64) * 128;

#pragma unroll
        for (int ksp = 0; ksp < 2; ksp++) {
            uint32_t af[2][2][4];
#pragma unroll
            for (int mi = 0; mi < 2; mi++)
#pragma unroll
                for (int kss = 0; kss < 2; kss++) {
                    const int ks = ksp * 2 + kss;
                    const int row = mi * 16 + (lane & 15);
                    const int c16 = ks * 2 + (lane >> 4);
                    ldsm_x4(abase + (uint32_t)(row * 128) +
                            (((uint32_t)(c16 ^ (row & 7))) << 4), af[mi][kss]);
                }
#pragma unroll
            for (int g = 0; g < 8; g++) {
                const int rowb = g * 8 + (lane & 7);
                const int c16 = ksp * 4 + (lane >> 3);
                uint32_t bf4[4];
                ldsm_x4(bbase + (uint32_t)(rowb * 128) +
                        (((uint32_t)(c16 ^ (rowb & 7))) << 4), bf4);
#pragma unroll
                for (int mi = 0; mi < 2; mi++) {
                    mma_tf32(acc[mi][g], af[mi][0], bf4[0], bf4[1]);
                    mma_tf32(acc[mi][g], af[mi][1], bf4[2], bf4[3]);
                }
            }
        }
        __syncthreads();
    }

    const int colb = n0 + warp_n * 64 + (lane & 3) * 2;

    if (!doRope) {
        // V: bf16 hi/lo split
#pragma unroll
        for (int mi = 0; mi < 2; mi++) {
            const int row = m0 + warp_m * 32 + mi * 16 + (lane >> 2);
#pragma unroll
            for (int ni = 0; ni < 8; ni++) {
                const int col = colb + ni * 8;
                const float bx = bias[col], by = bias[col + 1];
                uint32_t h2, l2;
                pack_split(acc[mi][ni][0] + bx, acc[mi][ni][1] + by, h2, l2);
                *(uint32_t*)&avh[(size_t)row * DMODEL + col] = h2;
                *(uint32_t*)&avl[(size_t)row * DMODEL + col] = l2;
                pack_split(acc[mi][ni][2] + bx, acc[mi][ni][3] + by, h2, l2);
                *(uint32_t*)&avh[(size_t)(row + 8) * DMODEL + col] = h2;
                *(uint32_t*)&avl[(size_t)(row + 8) * DMODEL + col] = l2;
            }
        }
    } else {
        // Q/K: RoPE + scale -> rna fp32. Pairs (j, j+32) = (ni, ni+4).
#pragma unroll
        for (int mi = 0; mi < 2; mi++) {
#pragma unroll
            for (int half = 0; half < 2; half++) {
                const int row = m0 + warp_m * 32 + mi * 16 + (lane >> 2) + half * 8;
                const int eo = half * 2;
                const float pos = (float)((row % L) * posStride);
#pragma unroll
                for (int nj = 0; nj < 4; nj++) {
                    const int col = colb + nj * 8;
                    float y1[2], y2[2];
#pragma unroll
                    for (int el = 0; el < 2; el++) {
                        const int j32 = nj * 8 + (lane & 3) * 2 + el;
                        const float invf =
                            1.0f / powf(10000.0f, (float)j32 * (1.0f / 32.0f));
                        float s, c;
                        sincosf(pos * invf, &s, &c);
                        const float x1 = acc[mi][nj][eo + el] + bias[col + el];
                        const float x2 = acc[mi][nj + 4][eo + el] + bias[col + 32 + el];
                        y1[el] = (x1 * c - x2 * s) * scale;
                        y2[el] = (x2 * c + x1 * s) * scale;
                    }
                    *(float2*)&Fo[(size_t)row * DMODEL + col] =
                        make_float2(__uint_as_float(rna_tf32(y1[0])),
                                    __uint_as_float(rna_tf32(y1[1])));
                    *(float2*)&Fo[(size_t)row * DMODEL + col + 32] =
                        make_float2(__uint_as_float(rna_tf32(y2[0])),
                                    __uint_as_float(rna_tf32(y2[1])));
                }
            }
        }
    }
}

// ---------------------------------------------------------------------------
// Output-projection GEMM — bf16 3-term (validated; kept for accuracy).
// ---------------------------------------------------------------------------
#define NCHUNK 48

__global__ __launch_bounds__(256, 2)
void mma_gemm_o(const __nv_bfloat16* __restrict__ Ahi, const __nv_bfloat16* __restrict__ Alo,
                const __nv_bfloat16* __restrict__ Whi, const __nv_bfloat16* __restrict__ Wlo,
                const float* __restrict__ bias, float* __restrict__ C)
{
    extern __shared__ char smc[];
    const uint32_t sbase = smem_u32(smc);
    const int tid = threadIdx.x;
    const int lane = tid & 31;
    const int wid = tid >> 5;
    const int warp_m = wid & 3;
    const int warp_n = wid >> 2;
    const int m0 = blockIdx.y * 128;
    const int n0 = blockIdx.x * 128;

    const int lc = tid & 7;
    const int lr = tid >> 3;

    float acc[2][8][4];
#pragma unroll
    for (int mi = 0; mi < 2; mi++)
#pragma unroll
        for (int ni = 0; ni < 8; ni++)
#pragma unroll
            for (int e = 0; e < 4; e++) acc[mi][ni][e] = 0.f;

    auto issue_load = [&](int ci) {
        const int seg = ci >> 4;
        const int kk = (ci & 15) << 6;
        const __nv_bfloat16* As = (seg == 1) ? Alo : Ahi;
        const __nv_bfloat16* Ws = (seg == 2) ? Wlo : Whi;
        const uint32_t aoff = (ci & 1) ? 32768u : 0u;
        const uint32_t da = sbase + aoff;
        const uint32_t db = sbase + aoff + 16384u;
        const uint32_t sw = ((uint32_t)(lc ^ (lr & 7))) << 4;
#pragma unroll
        for (int p = 0; p < 4; p++) {
            const int r = lr + p * 32;
            const uint32_t so = (uint32_t)(r * 128) + sw;
            cp16(da + so, As + (size_t)(m0 + r) * DMODEL + kk + lc * 8);
            cp16(db + so, Ws + (size_t)(n0 + r) * DMODEL + kk + lc * 8);
        }
    };

    issue_load(0);
    cp_commit();

    for (int i = 0; i < NCHUNK; i++) {
        if (i + 1 < NCHUNK) {
            issue_load(i + 1);
            cp_commit();
            cp_wait1();
        } else {
            cp_wait0();
        }
        __syncthreads();

        const uint32_t aoff = (i & 1) ? 32768u : 0u;
        const uint32_t abase = sbase + aoff + (uint32_t)(warp_m * 32) * 128;
        const uint32_t bbase = sbase + aoff + 16384u + (uint32_t)(warp_n * 64) * 128;

#pragma unroll
        for (int ks = 0; ks < 4; ks++) {
            uint32_t afr[2][4];
#pragma unroll
            for (int mi = 0; mi < 2; mi++) {
                const int row = mi * 16 + (lane & 15);
                const int ch = ks * 2 + (lane >> 4);
                ldsm_x4(abase + (uint32_t)(row * 128) + (((uint32_t)(ch ^ (row & 7))) << 4),
                        afr[mi]);
            }
#pragma unroll
            for (int g = 0; g < 4; g++) {
                const int n = g * 16 + (lane & 7) + ((lane & 16) >> 1);
                const int ch = ks * 2 + ((lane >> 3) & 1);
                uint32_t bfr[4];
                ldsm_x4(bbase + (uint32_t)(n * 128) + (((uint32_t)(ch ^ (n & 7))) << 4), bfr);
#pragma unroll
                for (int mi = 0; mi < 2; mi++) {
                    mma_bf16(acc[mi][2 * g + 0], afr[mi], bfr[0], bfr[1]);
                    mma_bf16(acc[mi][2 * g + 1], afr[mi], bfr[2], bfr[3]);
                }
            }
        }
        __syncthreads();
    }

    const int colb = n0 + warp_n * 64 + (lane & 3) * 2;
#pragma unroll
    for (int mi = 0; mi < 2; mi++) {
        const int row = m0 + warp_m * 32 + mi * 16 + (lane >> 2);
#pragma unroll
        for (int ni = 0; ni < 8; ni++) {
            const int col = colb + ni * 8;
            const float bx = bias[col], by = bias[col + 1];
            *(float2*)&C[(size_t)row * DMODEL + col] =
                make_float2(acc[mi][ni][0] + bx, acc[mi][ni][1] + by);
            *(float2*)&C[(size_t)(row + 8) * DMODEL + col] =
                make_float2(acc[mi][ni][2] + bx, acc[mi][ni][3] + by);
        }
    }
}

// ---------------------------------------------------------------------------
// Flash attention: S via tf32 (Q/K rna fp32), PV via bf16 3-term.
// smem 96KB: QT (tf32, 32KB persistent; 2 phys 128B rows per q-row) +
// 2 stages x (K tf32 16KB + VH 8KB + VL 8KB).
// sacc[gn] covers keys gn*8..+7 (same C layout as before -> softmax/PV reuse).
// ---------------------------------------------------------------------------
#define ATTN_SMEM 98304
#define NKCH (SK / 64)

__global__ __launch_bounds__(256, 2)
void attn_mma(const float* __restrict__ Qf, const float* __restrict__ Kf,
              const __nv_bfloat16* __restrict__ Vh, const __nv_bfloat16* __restrict__ Vl,
              __nv_bfloat16* __restrict__ Oh, __nv_bfloat16* __restrict__ Ol)
{
    extern __shared__ char smc[];
    const uint32_t sbase = smem_u32(smc);
    const int tid = threadIdx.x;
    const int lane = tid & 31;
    const int wid = tid >> 5;
    const int b = blockIdx.z;
    const int h = blockIdx.y;
    const int s0 = blockIdx.x * 128;

    const uint32_t QT = 0;            // 32KB persistent (256 phys rows x 128B)
    const uint32_t STG0 = 32768;      // 2 x 32KB stages: K @0, VH @16K, VL @24K

    // ---- Q load: phys row p = tid (q = p>>1, half = p&1), 8 cp16 each ----
    {
        const int p = tid;
        const int q = p >> 1;
        const int half = p & 1;
        const float* src = Qf + ((size_t)(b * SQ + s0 + q)) * DMODEL + h * HD + half * 32;
#pragma unroll
        for (int c = 0; c < 8; c++) {
            const uint32_t off = (uint32_t)(p * 128) + (((uint32_t)(c ^ (p & 7))) << 4);
            cp16(sbase + QT + off, src + c * 4);
        }
    }
    cp_commit();

    auto issue_kv = [&](int ci) {
        const uint32_t st = STG0 + (uint32_t)(ci & 1) * 32768u;
        // K tf32: 128 phys rows x 128B; thread: p2 = tid>>1, 4 cols
        {
            const int p2 = tid >> 1;
            const int key = p2 >> 1;
            const int half = p2 & 1;
            const int cc = (tid & 1) * 4;
            const float* src =
                Kf + ((size_t)(b * SK + ci * 64 + key)) * DMODEL + h * HD + half * 32;
#pragma unroll
            for (int u = 0; u < 4; u++) {
                const int c = cc + u;
                const uint32_t off = (uint32_t)(p2 * 128) + (((uint32_t)(c ^ (p2 & 7))) << 4);
                cp16(sbase + st + off, src + c * 4);
            }
        }
        // V bf16 hi/lo: 64 rows x 128B each
        {
            const int r = tid >> 2;
            const int cb = (tid & 3) * 2;
            const size_t src = ((size_t)(b * SK + ci * 64 + r)) * DMODEL + h * HD;
#pragma unroll
            for (int u = 0; u < 2; u++) {
                const int c = cb + u;
                const uint32_t off = (uint32_t)(r * 128) + (((uint32_t)(c ^ (r & 7))) << 4);
                cp16(sbase + st + 16384u + off, Vh + src + c * 8);
                cp16(sbase + st + 24576u + off, Vl + src + c * 8);
            }
        }
    };

    issue_kv(0);
    cp_commit();

    float oacc[8][4];
#pragma unroll
    for (int g = 0; g < 8; g++)
#pragma unroll
        for (int e = 0; e < 4; e++) oacc[g][e] = 0.f;
    float m0 = -INFINITY, m1 = -INFINITY, l0 = 0.f, l1 = 0.f;

    const int qrow = wid * 16 + (lane & 15);

    for (int i = 0; i < NKCH; i++) {
        if (i + 1 < NKCH) {
            issue_kv(i + 1);
            cp_commit();
            cp_wait1();
        } else {
            cp_wait0();
        }
        __syncthreads();

        const uint32_t st = sbase + STG0 + (uint32_t)(i & 1) * 32768u;
        const uint32_t kb = st;
        const uint32_t vh = st + 16384u, vl = st + 24576u;

        // ---- S = Q K^T via tf32 (sacc[gn] = keys gn*8..+7) ----
        float sacc[8][4];
#pragma unroll
        for (int g = 0; g < 8; g++)
#pragma unroll
            for (int e = 0; e < 4; e++) sacc[g][e] = 0.f;

#pragma unroll
        for (int ksp = 0; ksp < 4; ksp++) {
            uint32_t af[2][4];
#pragma unroll
            for (int kss = 0; kss < 2; kss++) {
                const int ks = ksp * 2 + kss;
                const int pr = qrow * 2 + (ks >> 2);
                const int c16 = (ks & 3) * 2 + (lane >> 4);
                ldsm_x4(sbase + QT + (uint32_t)(pr * 128) +
                        (((uint32_t)(c16 ^ (pr & 7))) << 4), af[kss]);
            }
#pragma unroll
            for (int gn = 0; gn < 8; gn++) {
                const int key = gn * 8 + (lane & 7);
                const int pr = key * 2 + (ksp >> 1);
                const int c16 = (ksp & 1) * 4 + (lane >> 3);
                uint32_t bf4[4];
                ldsm_x4(kb + (uint32_t)(pr * 128) + (((uint32_t)(c16 ^ (pr & 7))) << 4), bf4);
                mma_tf32(sacc[gn], af[0], bf4[0], bf4[1]);
                mma_tf32(sacc[gn], af[1], bf4[2], bf4[3]);
            }
        }

        // ---- online softmax (unchanged) ----
        float mx0 = sacc[0][0], mx1 = sacc[0][2];
#pragma unroll
        for (int g = 0; g < 8; g++) {
            mx0 = fmaxf(mx0, fmaxf(sacc[g][0], sacc[g][1]));
            mx1 = fmaxf(mx1, fmaxf(sacc[g][2], sacc[g][3]));
        }
        mx0 = fmaxf(mx0, __shfl_xor_sync(0xffffffffu, mx0, 1));
        mx0 = fmaxf(mx0, __shfl_xor_sync(0xffffffffu, mx0, 2));
        mx1 = fmaxf(mx1, __shfl_xor_sync(0xffffffffu, mx1, 1));
        mx1 = fmaxf(mx1, __shfl_xor_sync(0xffffffffu, mx1, 2));
        const float mn0 = fmaxf(m0, mx0);
        const float mn1 = fmaxf(m1, mx1);
        const float a0 = fast_exp(m0 - mn0);
        const float a1 = fast_exp(m1 - mn1);
        m0 = mn0; m1 = mn1;
        float s0s = 0.f, s1s = 0.f;
#pragma unroll
        for (int g = 0; g < 8; g++) {
            sacc[g][0] = fast_exp(sacc[g][0] - mn0);
            sacc[g][1] = fast_exp(sacc[g][1] - mn0);
            sacc[g][2] = fast_exp(sacc[g][2] - mn1);
            sacc[g][3] = fast_exp(sacc[g][3] - mn1);
            s0s += sacc[g][0] + sacc[g][1];
            s1s += sacc[g][2] + sacc[g][3];
        }
        l0 = l0 * a0 + s0s;
        l1 = l1 * a1 + s1s;
#pragma unroll
        for (int g = 0; g < 8; g++) {
            oacc[g][0] *= a0; oacc[g][1] *= a0;
            oacc[g][2] *= a1; oacc[g][3] *= a1;
        }

        // ---- O += P V (bf16 3-term, unchanged) ----
#pragma unroll
        for (int ks = 0; ks < 4; ks++) {
            uint32_t ah[4], al[4];
            pack_split(sacc[2 * ks][0],     sacc[2 * ks][1],     ah[0], al[0]);
            pack_split(sacc[2 * ks][2],     sacc[2 * ks][3],     ah[1], al[1]);
            pack_split(sacc[2 * ks + 1][0], sacc[2 * ks + 1][1], ah[2], al[2]);
            pack_split(sacc[2 * ks + 1][2], sacc[2 * ks + 1][3], ah[3], al[3]);
            const int tile2 = lane >> 3;
            const int key = ks * 16 + (tile2 & 1) * 8 + (lane & 7);
#pragma unroll
            for (int g = 0; g < 4; g++) {
                const int c = g * 2 + (tile2 >> 1);
                const uint32_t off = (uint32_t)(key * 128) + (((uint32_t)(c ^ (key & 7))) << 4);
                uint32_t bh[4], bl[4];
                ldsm_x4t(vh + off, bh);
                ldsm_x4t(vl + off, bl);
                mma_bf16(oacc[2 * g + 0], ah, bh[0], bh[1]);
                mma_bf16(oacc[2 * g + 0], al, bh[0], bh[1]);
                mma_bf16(oacc[2 * g + 0], ah, bl[0], bl[1]);
                mma_bf16(oacc[2 * g + 1], ah, bh[2], bh[3]);
                mma_bf16(oacc[2 * g + 1], al, bh[2], bh[3]);
                mma_bf16(oacc[2 * g + 1], ah, bl[2], bl[3]);
            }
        }
        __syncthreads();
    }

    l0 += __shfl_xor_sync(0xffffffffu, l0, 1);
    l0 += __shfl_xor_sync(0xffffffffu, l0, 2);
    l1 += __shfl_xor_sync(0xffffffffu, l1, 1);
    l1 += __shfl_xor_sync(0xffffffffu, l1, 2);
    const float inv0 = 1.0f / l0;
    const float inv1 = 1.0f / l1;
    const int r0 = s0 + wid * 16 + (lane >> 2);
#pragma unroll
    for (int g = 0; g < 8; g++) {
        const int col = h * HD + g * 8 + (lane & 3) * 2;
        uint32_t h2, l2;
        pack_split(oacc[g][0] * inv0, oacc[g][1] * inv0, h2, l2);
        *(uint32_t*)&Oh[((size_t)(b * SQ) + r0) * DMODEL + col] = h2;
        *(uint32_t*)&Ol[((size_t)(b * SQ) + r0) * DMODEL + col] = l2;
        pack_split(oacc[g][2] * inv1, oacc[g][3] * inv1, h2, l2);
        *(uint32_t*)&Oh[((size_t)(b * SQ) + r0 + 8) * DMODEL + col] = h2;
        *(uint32_t*)&Ol[((size_t)(b * SQ) + r0 + 8) * DMODEL + col] = l2;
    }
}

// ---------------------------------------------------------------------------
extern "C" void kernel_launch(void* const* d_in, const int* in_sizes, int n_in,
                              void* d_out, int out_size)
{
    const float* query = (const float*)d_in[0];
    const float* kv    = (const float*)d_in[1];
    const float* q_w   = (const float*)d_in[2];
    const float* q_b   = (const float*)d_in[3];
    const float* k_w   = (const float*)d_in[4];
    const float* k_b   = (const float*)d_in[5];
    const float* v_w   = (const float*)d_in[6];
    const float* v_b   = (const float*)d_in[7];
    const float* out_w = (const float*)d_in[8];
    const float* out_b = (const float*)d_in[9];
    float* out = (float*)d_out;

    float *qr, *kvr, *wqr, *wkr, *wvr, *aq, *ak;
    __nv_bfloat16 *woh, *wol, *oh, *ol, *avh, *avl;
    cudaGetSymbolAddress((void**)&qr,  g_qr);  cudaGetSymbolAddress((void**)&kvr, g_kvr);
    cudaGetSymbolAddress((void**)&wqr, g_wqr); cudaGetSymbolAddress((void**)&wkr, g_wkr);
    cudaGetSymbolAddress((void**)&wvr, g_wvr);
    cudaGetSymbolAddress((void**)&woh, g_woh); cudaGetSymbolAddress((void**)&wol, g_wol);
    cudaGetSymbolAddress((void**)&oh,  g_oh);  cudaGetSymbolAddress((void**)&ol,  g_ol);
    cudaGetSymbolAddress((void**)&aq,  g_aq);  cudaGetSymbolAddress((void**)&ak,  g_ak);
    cudaGetSymbolAddress((void**)&avh, g_avh); cudaGetSymbolAddress((void**)&avl, g_avl);

    // launch 0: rna-round operands + bf16-split out_w
    round_all<<<16384, 256>>>(q_w, k_w, v_w, out_w, query, kv,
                              wqr, wkr, wvr, woh, wol, qr, kvr);

    // launch 1: merged tf32 Q/K/V projections
    cudaFuncSetAttribute(mma_gemm_qkv, cudaFuncAttributeMaxDynamicSharedMemorySize, GEMM_SMEM);
    mma_gemm_qkv<<<dim3(8, 160), 256, GEMM_SMEM>>>(qr, kvr, wqr, wkr, wvr,
                                                   q_b, k_b, v_b,
                                                   aq, ak, avh, avl);

    // launch 2: attention (tf32 S, bf16 3-term PV)
    cudaFuncSetAttribute(attn_mma, cudaFuncAttributeMaxDynamicSharedMemorySize, ATTN_SMEM);
    attn_mma<<<dim3(SQ / 128, NHEAD, NB), 256, ATTN_SMEM>>>(aq, ak, avh, avl, oh, ol);

    // launch 3: output projection (bf16 3-term, fp32 out)
    cudaFuncSetAttribute(mma_gemm_o, cudaFuncAttributeMaxDynamicSharedMemorySize, GEMM_SMEM);
    mma_gemm_o<<<dim3(8, 32), 256, GEMM_SMEM>>>(oh, ol, woh, wol, out_b, out);
}

// round 17
// speedup vs baseline: 1.0996x; 1.0996x over previous
#include <cuda_runtime.h>
#include <cuda_bf16.h>
#include <math.h>
#include <stdint.h>

#define DMODEL 1024
#define NHEAD  16
#define HD     64
#define NB     4
#define SQ     1024
#define SK     2048

// ---------------------------------------------------------------------------
// Scratch (__device__ globals)
// ---------------------------------------------------------------------------
// tf32-rounded fp32 GEMM operands
__device__ float g_qr[NB * SQ * DMODEL];
__device__ float g_kvr[NB * SK * DMODEL];
__device__ float g_wqr[DMODEL * DMODEL];
__device__ float g_wkr[DMODEL * DMODEL];
__device__ float g_wvr[DMODEL * DMODEL];
__device__ float g_wor[DMODEL * DMODEL];
// attention operands (bf16 hi/lo, post-RoPE) — R15-validated layout
__device__ __nv_bfloat16 g_aqh[NB * SQ * DMODEL];
__device__ __nv_bfloat16 g_aql[NB * SQ * DMODEL];
__device__ __nv_bfloat16 g_akh[NB * SK * DMODEL];
__device__ __nv_bfloat16 g_akl[NB * SK * DMODEL];
__device__ __nv_bfloat16 g_avh[NB * SK * DMODEL];
__device__ __nv_bfloat16 g_avl[NB * SK * DMODEL];
// attention output (rna fp32, feeds tf32 O-projection)
__device__ float g_ofp[NB * SQ * DMODEL];

// ---------------------------------------------------------------------------
// Helpers
// ---------------------------------------------------------------------------
__device__ __forceinline__ uint32_t smem_u32(const void* p) {
    uint32_t a;
    asm("{ .reg .u64 t; cvta.to.shared.u64 t, %1; cvt.u32.u64 %0, t; }" : "=r"(a) : "l"(p));
    return a;
}
__device__ __forceinline__ void cp16(uint32_t dst, const void* src) {
    asm volatile("cp.async.cg.shared.global [%0], [%1], 16;" :: "r"(dst), "l"(src));
}
__device__ __forceinline__ void cp_commit() {
    asm volatile("cp.async.commit_group;" ::: "memory");
}
__device__ __forceinline__ void cp_wait1() {
    asm volatile("cp.async.wait_group 1;" ::: "memory");
}
__device__ __forceinline__ void cp_wait0() {
    asm volatile("cp.async.wait_group 0;" ::: "memory");
}
__device__ __forceinline__ void ldsm_x4(uint32_t addr, uint32_t* r) {
    asm volatile("ldmatrix.sync.aligned.m8n8.x4.shared.b16 {%0,%1,%2,%3}, [%4];"
                 : "=r"(r[0]), "=r"(r[1]), "=r"(r[2]), "=r"(r[3]) : "r"(addr));
}
__device__ __forceinline__ void ldsm_x4t(uint32_t addr, uint32_t* r) {
    asm volatile("ldmatrix.sync.aligned.m8n8.x4.trans.shared.b16 {%0,%1,%2,%3}, [%4];"
                 : "=r"(r[0]), "=r"(r[1]), "=r"(r[2]), "=r"(r[3]) : "r"(addr));
}
__device__ __forceinline__ void mma_bf16(float* d, const uint32_t* a, uint32_t b0, uint32_t b1) {
    asm volatile(
        "mma.sync.aligned.m16n8k16.row.col.f32.bf16.bf16.f32 "
        "{%0,%1,%2,%3}, {%4,%5,%6,%7}, {%8,%9}, {%0,%1,%2,%3};"
        : "+f"(d[0]), "+f"(d[1]), "+f"(d[2]), "+f"(d[3])
        : "r"(a[0]), "r"(a[1]), "r"(a[2]), "r"(a[3]), "r"(b0), "r"(b1));
}
__device__ __forceinline__ void mma_tf32(float* d, const uint32_t* a, uint32_t b0, uint32_t b1) {
    asm volatile(
        "mma.sync.aligned.m16n8k8.row.col.f32.tf32.tf32.f32 "
        "{%0,%1,%2,%3}, {%4,%5,%6,%7}, {%8,%9}, {%0,%1,%2,%3};"
        : "+f"(d[0]), "+f"(d[1]), "+f"(d[2]), "+f"(d[3])
        : "r"(a[0]), "r"(a[1]), "r"(a[2]), "r"(a[3]), "r"(b0), "r"(b1));
}
__device__ __forceinline__ uint32_t rna_tf32(float x) {
    uint32_t r;
    asm("cvt.rna.tf32.f32 %0, %1;" : "=r"(r) : "f"(x));
    return r;
}
// exp on the FMA pipe: 2^(x*log2e), deg-5 poly. rel err ~5e-7.
__device__ __forceinline__ float fast_exp(float x) {
    float y = fmaxf(x * 1.4426950408889634f, -100.0f);
    int n = __float2int_rn(y);
    float f = y - (float)n;
    float p = 1.3333558146e-3f;
    p = fmaf(p, f, 9.6181291076e-3f);
    p = fmaf(p, f, 5.5504108665e-2f);
    p = fmaf(p, f, 2.4022650696e-1f);
    p = fmaf(p, f, 6.9314718056e-1f);
    p = fmaf(p, f, 1.0f);
    return __int_as_float(__float_as_int(p) + (n << 23));
}
// split (a,b) fp32 pair -> bf16x2 hi + bf16x2 lo (lo = residual)
__device__ __forceinline__ void pack_split(float a, float b, uint32_t& hi2, uint32_t& lo2) {
    __nv_bfloat162 hb = __float22bfloat162_rn(make_float2(a, b));
    uint32_t h;
    memcpy(&h, &hb, 4);
    float ra = a - __uint_as_float(h << 16);
    float rb = b - __uint_as_float(h & 0xFFFF0000u);
    __nv_bfloat162 lb = __float22bfloat162_rn(make_float2(ra, rb));
    uint32_t l;
    memcpy(&l, &lb, 4);
    hi2 = h; lo2 = l;
}

// ---------------------------------------------------------------------------
// Pre-pass: segs (each 2^20): 0-3 q/k/v/out weights -> rna fp32;
// 4-7 query -> rna; 8-15 kv -> rna.
// ---------------------------------------------------------------------------
#define NWE (DMODEL * DMODEL)

__global__ void round_all(const float* __restrict__ q_w, const float* __restrict__ k_w,
                          const float* __restrict__ v_w, const float* __restrict__ o_w,
                          const float* __restrict__ query, const float* __restrict__ kvp,
                          float* __restrict__ wqr, float* __restrict__ wkr,
                          float* __restrict__ wvr, float* __restrict__ wor,
                          float* __restrict__ qr, float* __restrict__ kvr)
{
    const long long i = (long long)(blockIdx.x * blockDim.x + threadIdx.x) * 4;
    const int seg = (int)(i >> 20);

    const float* src;
    float* dst;
    long long off;
    if (seg < 4) {
        off = i & (NWE - 1);
        src = (seg == 0) ? q_w : (seg == 1) ? k_w : (seg == 2) ? v_w : o_w;
        dst = (seg == 0) ? wqr : (seg == 1) ? wkr : (seg == 2) ? wvr : wor;
    } else if (seg < 8) {
        off = i - 4LL * NWE;
        src = query; dst = qr;
    } else {
        off = i - 8LL * NWE;
        src = kvp; dst = kvr;
    }
    float4 v = *(const float4*)(src + off);
    float4 o;
    o.x = __uint_as_float(rna_tf32(v.x));
    o.y = __uint_as_float(rna_tf32(v.y));
    o.z = __uint_as_float(rna_tf32(v.z));
    o.w = __uint_as_float(rna_tf32(v.w));
    *(float4*)(dst + off) = o;
}

// ---------------------------------------------------------------------------
// tf32 merged Q/K/V projection GEMM (R15-validated). Grid (8, 160).
// Epilogues: Q/K -> RoPE + scale -> bf16 hi/lo; V -> bf16 hi/lo.
// ---------------------------------------------------------------------------
#define GEMM_SMEM 65536
#define NCH32 32

__global__ __launch_bounds__(256, 2)
void mma_gemm_qkv(const float* __restrict__ qr, const float* __restrict__ kvr,
                  const float* __restrict__ wqr, const float* __restrict__ wkr,
                  const float* __restrict__ wvr,
                  const float* __restrict__ q_b, const float* __restrict__ k_b,
                  const float* __restrict__ v_b,
                  __nv_bfloat16* __restrict__ aqh, __nv_bfloat16* __restrict__ aql,
                  __nv_bfloat16* __restrict__ akh, __nv_bfloat16* __restrict__ akl,
                  __nv_bfloat16* __restrict__ avh, __nv_bfloat16* __restrict__ avl)
{
    extern __shared__ char smc[];
    const uint32_t sbase = smem_u32(smc);
    const int tid = threadIdx.x;
    const int lane = tid & 31;
    const int wid = tid >> 5;
    const int warp_m = wid & 3;
    const int warp_n = wid >> 2;
    const int y = blockIdx.y;
    const int n0 = blockIdx.x * 128;

    const float *A, *W, *bias;
    __nv_bfloat16 *Oh, *Ol;
    int m0, L, posStride, doRope;
    float scale;
    if (y < 32) {
        A = qr; W = wqr; bias = q_b; Oh = aqh; Ol = aql; m0 = y * 128;
        L = SQ; posStride = 2; scale = 0.125f; doRope = 1;
    } else if (y < 96) {
        A = kvr; W = wkr; bias = k_b; Oh = akh; Ol = akl; m0 = (y - 32) * 128;
        L = SK; posStride = 1; scale = 1.0f; doRope = 1;
    } else {
        A = kvr; W = wvr; bias = v_b; Oh = avh; Ol = avl; m0 = (y - 96) * 128;
        L = 0; posStride = 0; scale = 0.f; doRope = 0;
    }

    const int lc = tid & 7;
    const int lr = tid >> 3;

    float acc[2][8][4];
#pragma unroll
    for (int mi = 0; mi < 2; mi++)
#pragma unroll
        for (int ni = 0; ni < 8; ni++)
#pragma unroll
            for (int e = 0; e < 4; e++) acc[mi][ni][e] = 0.f;

    auto issue_load = [&](int ci) {
        const int kk = ci * 32;
        const uint32_t st = (ci & 1) ? 32768u : 0u;
        const uint32_t da = sbase + st;
        const uint32_t db = sbase + st + 16384u;
        const uint32_t sw = ((uint32_t)(lc ^ (lr & 7))) << 4;
#pragma unroll
        for (int p = 0; p < 4; p++) {
            const int r = lr + p * 32;
            const uint32_t so = (uint32_t)(r * 128) + sw;
            cp16(da + so, A + (size_t)(m0 + r) * DMODEL + kk + lc * 4);
            cp16(db + so, W + (size_t)(n0 + r) * DMODEL + kk + lc * 4);
        }
    };

    issue_load(0);
    cp_commit();

    for (int i = 0; i < NCH32; i++) {
        if (i + 1 < NCH32) {
            issue_load(i + 1);
            cp_commit();
            cp_wait1();
        } else {
            cp_wait0();
        }
        __syncthreads();

        const uint32_t st = (i & 1) ? 32768u : 0u;
        const uint32_t abase = sbase + st + (uint32_t)(warp_m * 32) * 128;
        const uint32_t bbase = sbase + st + 16384u + (uint32_t)(warp_n * 64) * 128;

#pragma unroll
        for (int ksp = 0; ksp < 2; ksp++) {
            uint32_t af[2][2][4];
#pragma unroll
            for (int mi = 0; mi < 2; mi++)
#pragma unroll
                for (int kss = 0; kss < 2; kss++) {
                    const int ks = ksp * 2 + kss;
                    const int row = mi * 16 + (lane & 15);
                    const int c16 = ks * 2 + (lane >> 4);
                    ldsm_x4(abase + (uint32_t)(row * 128) +
                            (((uint32_t)(c16 ^ (row & 7))) << 4), af[mi][kss]);
                }
#pragma unroll
            for (int g = 0; g < 8; g++) {
                const int rowb = g * 8 + (lane & 7);
                const int c16 = ksp * 4 + (lane >> 3);
                uint32_t bf4[4];
                ldsm_x4(bbase + (uint32_t)(rowb * 128) +
                        (((uint32_t)(c16 ^ (rowb & 7))) << 4), bf4);
#pragma unroll
                for (int mi = 0; mi < 2; mi++) {
                    mma_tf32(acc[mi][g], af[mi][0], bf4[0], bf4[1]);
                    mma_tf32(acc[mi][g], af[mi][1], bf4[2], bf4[3]);
                }
            }
        }
        __syncthreads();
    }

    const int colb = n0 + warp_n * 64 + (lane & 3) * 2;

    if (!doRope) {
#pragma unroll
        for (int mi = 0; mi < 2; mi++) {
            const int row = m0 + warp_m * 32 + mi * 16 + (lane >> 2);
#pragma unroll
            for (int ni = 0; ni < 8; ni++) {
                const int col = colb + ni * 8;
                const float bx = bias[col], by = bias[col + 1];
                uint32_t h2, l2;
                pack_split(acc[mi][ni][0] + bx, acc[mi][ni][1] + by, h2, l2);
                *(uint32_t*)&Oh[(size_t)row * DMODEL + col] = h2;
                *(uint32_t*)&Ol[(size_t)row * DMODEL + col] = l2;
                pack_split(acc[mi][ni][2] + bx, acc[mi][ni][3] + by, h2, l2);
                *(uint32_t*)&Oh[(size_t)(row + 8) * DMODEL + col] = h2;
                *(uint32_t*)&Ol[(size_t)(row + 8) * DMODEL + col] = l2;
            }
        }
    } else {
#pragma unroll
        for (int mi = 0; mi < 2; mi++) {
#pragma unroll
            for (int half = 0; half < 2; half++) {
                const int row = m0 + warp_m * 32 + mi * 16 + (lane >> 2) + half * 8;
                const int eo = half * 2;
                const float pos = (float)((row % L) * posStride);
#pragma unroll
                for (int nj = 0; nj < 4; nj++) {
                    const int col = colb + nj * 8;
                    float y1[2], y2[2];
#pragma unroll
                    for (int el = 0; el < 2; el++) {
                        const int j32 = nj * 8 + (lane & 3) * 2 + el;
                        const float invf =
                            1.0f / powf(10000.0f, (float)j32 * (1.0f / 32.0f));
                        float s, c;
                        sincosf(pos * invf, &s, &c);
                        const float x1 = acc[mi][nj][eo + el] + bias[col + el];
                        const float x2 = acc[mi][nj + 4][eo + el] + bias[col + 32 + el];
                        y1[el] = (x1 * c - x2 * s) * scale;
                        y2[el] = (x2 * c + x1 * s) * scale;
                    }
                    uint32_t h2, l2;
                    pack_split(y1[0], y1[1], h2, l2);
                    *(uint32_t*)&Oh[(size_t)row * DMODEL + col] = h2;
                    *(uint32_t*)&Ol[(size_t)row * DMODEL + col] = l2;
                    pack_split(y2[0], y2[1], h2, l2);
                    *(uint32_t*)&Oh[(size_t)row * DMODEL + col + 32] = h2;
                    *(uint32_t*)&Ol[(size_t)row * DMODEL + col + 32] = l2;
                }
            }
        }
    }
}

// ---------------------------------------------------------------------------
// O-projection GEMM — tf32 single-pass (validated mainloop shape), fp32 out.
// ---------------------------------------------------------------------------
__global__ __launch_bounds__(256, 2)
void mma_gemm_o(const float* __restrict__ A, const float* __restrict__ W,
                const float* __restrict__ bias, float* __restrict__ C)
{
    extern __shared__ char smc[];
    const uint32_t sbase = smem_u32(smc);
    const int tid = threadIdx.x;
    const int lane = tid & 31;
    const int wid = tid >> 5;
    const int warp_m = wid & 3;
    const int warp_n = wid >> 2;
    const int m0 = blockIdx.y * 128;
    const int n0 = blockIdx.x * 128;

    const int lc = tid & 7;
    const int lr = tid >> 3;

    float acc[2][8][4];
#pragma unroll
    for (int mi = 0; mi < 2; mi++)
#pragma unroll
        for (int ni = 0; ni < 8; ni++)
#pragma unroll
            for (int e = 0; e < 4; e++) acc[mi][ni][e] = 0.f;

    auto issue_load = [&](int ci) {
        const int kk = ci * 32;
        const uint32_t st = (ci & 1) ? 32768u : 0u;
        const uint32_t da = sbase + st;
        const uint32_t db = sbase + st + 16384u;
        const uint32_t sw = ((uint32_t)(lc ^ (lr & 7))) << 4;
#pragma unroll
        for (int p = 0; p < 4; p++) {
            const int r = lr + p * 32;
            const uint32_t so = (uint32_t)(r * 128) + sw;
            cp16(da + so, A + (size_t)(m0 + r) * DMODEL + kk + lc * 4);
            cp16(db + so, W + (size_t)(n0 + r) * DMODEL + kk + lc * 4);
        }
    };

    issue_load(0);
    cp_commit();

    for (int i = 0; i < NCH32; i++) {
        if (i + 1 < NCH32) {
            issue_load(i + 1);
            cp_commit();
            cp_wait1();
        } else {
            cp_wait0();
        }
        __syncthreads();

        const uint32_t st = (i & 1) ? 32768u : 0u;
        const uint32_t abase = sbase + st + (uint32_t)(warp_m * 32) * 128;
        const uint32_t bbase = sbase + st + 16384u + (uint32_t)(warp_n * 64) * 128;

#pragma unroll
        for (int ksp = 0; ksp < 2; ksp++) {
            uint32_t af[2][2][4];
#pragma unroll
            for (int mi = 0; mi < 2; mi++)
#pragma unroll
                for (int kss = 0; kss < 2; kss++) {
                    const int ks = ksp * 2 + kss;
                    const int row = mi * 16 + (lane & 15);
                    const int c16 = ks * 2 + (lane >> 4);
                    ldsm_x4(abase + (uint32_t)(row * 128) +
                            (((uint32_t)(c16 ^ (row & 7))) << 4), af[mi][kss]);
                }
#pragma unroll
            for (int g = 0; g < 8; g++) {
                const int rowb = g * 8 + (lane & 7);
                const int c16 = ksp * 4 + (lane >> 3);
                uint32_t bf4[4];
                ldsm_x4(bbase + (uint32_t)(rowb * 128) +
                        (((uint32_t)(c16 ^ (rowb & 7))) << 4), bf4);
#pragma unroll
                for (int mi = 0; mi < 2; mi++) {
                    mma_tf32(acc[mi][g], af[mi][0], bf4[0], bf4[1]);
                    mma_tf32(acc[mi][g], af[mi][1], bf4[2], bf4[3]);
                }
            }
        }
        __syncthreads();
    }

    const int colb = n0 + warp_n * 64 + (lane & 3) * 2;
#pragma unroll
    for (int mi = 0; mi < 2; mi++) {
        const int row = m0 + warp_m * 32 + mi * 16 + (lane >> 2);
#pragma unroll
        for (int ni = 0; ni < 8; ni++) {
            const int col = colb + ni * 8;
            const float bx = bias[col], by = bias[col + 1];
            *(float2*)&C[(size_t)row * DMODEL + col] =
                make_float2(acc[mi][ni][0] + bx, acc[mi][ni][1] + by);
            *(float2*)&C[(size_t)(row + 8) * DMODEL + col] =
                make_float2(acc[mi][ni][2] + bx, acc[mi][ni][3] + by);
        }
    }
}

// ---------------------------------------------------------------------------
// Flash attention — R15-validated bf16 3-term config; output -> rna fp32.
// ---------------------------------------------------------------------------
#define ATTN_SMEM 81920
#define NKCH (SK / 64)

__global__ __launch_bounds__(256, 2)
void attn_mma(const __nv_bfloat16* __restrict__ Qh, const __nv_bfloat16* __restrict__ Ql,
              const __nv_bfloat16* __restrict__ Kh, const __nv_bfloat16* __restrict__ Kl,
              const __nv_bfloat16* __restrict__ Vh, const __nv_bfloat16* __restrict__ Vl,
              float* __restrict__ Ofp)
{
    extern __shared__ char smc[];
    const uint32_t sbase = smem_u32(smc);
    const int tid = threadIdx.x;
    const int lane = tid & 31;
    const int wid = tid >> 5;
    const int b = blockIdx.z;
    const int h = blockIdx.y;
    const int s0 = blockIdx.x * 128;

    const uint32_t QLS = 0;
    const uint32_t STG0 = 16384;

    {
        const int r = tid >> 1;
        const int cb = (tid & 1) * 4;
        const size_t src = ((size_t)(b * SQ + s0 + r)) * DMODEL + h * HD;
#pragma unroll
        for (int u = 0; u < 4; u++) {
            const int c = cb + u;
            const uint32_t off = (uint32_t)(r * 128) + (((uint32_t)(c ^ (r & 7))) << 4);
            cp16(sbase + STG0 + off, Qh + src + c * 8);
            cp16(sbase + QLS + off, Ql + src + c * 8);
        }
    }
    cp_commit();
    cp_wait0();
    __syncthreads();

    uint32_t qfh[4][4];
    {
        const int row = wid * 16 + (lane & 15);
#pragma unroll
        for (int ks = 0; ks < 4; ks++) {
            const int ch = ks * 2 + (lane >> 4);
            const uint32_t off = (uint32_t)(row * 128) + (((uint32_t)(ch ^ (row & 7))) << 4);
            ldsm_x4(sbase + STG0 + off, qfh[ks]);
        }
    }
    __syncthreads();

    auto issue_kv = [&](int ci) {
        const uint32_t st = STG0 + (uint32_t)(ci & 1) * 32768u;
        const int r = tid >> 2;
        const int cb = (tid & 3) * 2;
        const size_t src = ((size_t)(b * SK + ci * 64 + r)) * DMODEL + h * HD;
#pragma unroll
        for (int u = 0; u < 2; u++) {
            const int c = cb + u;
            const uint32_t off = (uint32_t)(r * 128) + (((uint32_t)(c ^ (r & 7))) << 4);
            cp16(st + sbase + off, Kh + src + c * 8);
            cp16(st + sbase + 8192u + off, Kl + src + c * 8);
            cp16(st + sbase + 16384u + off, Vh + src + c * 8);
            cp16(st + sbase + 24576u + off, Vl + src + c * 8);
        }
    };

    issue_kv(0);
    cp_commit();

    float oacc[8][4];
#pragma unroll
    for (int g = 0; g < 8; g++)
#pragma unroll
        for (int e = 0; e < 4; e++) oacc[g][e] = 0.f;
    float m0 = -INFINITY, m1 = -INFINITY, l0 = 0.f, l1 = 0.f;

    const int qrow = wid * 16 + (lane & 15);

    for (int i = 0; i < NKCH; i++) {
        if (i + 1 < NKCH) {
            issue_kv(i + 1);
            cp_commit();
            cp_wait1();
        } else {
            cp_wait0();
        }
        __syncthreads();

        const uint32_t st = sbase + STG0 + (uint32_t)(i & 1) * 32768u;
        const uint32_t kh = st, kl = st + 8192u;
        const uint32_t vh = st + 16384u, vl = st + 24576u;

        float sacc[8][4];
#pragma unroll
        for (int g = 0; g < 8; g++)
#pragma unroll
            for (int e = 0; e < 4; e++) sacc[g][e] = 0.f;

#pragma unroll
        for (int ks = 0; ks < 4; ks++) {
            uint32_t qfl[4];
            {
                const int ch = ks * 2 + (lane >> 4);
                const uint32_t off =
                    (uint32_t)(qrow * 128) + (((uint32_t)(ch ^ (qrow & 7))) << 4);
                ldsm_x4(sbase + QLS + off, qfl);
            }
#pragma unroll
            for (int g = 0; g < 4; g++) {
                const int n = g * 16 + (lane & 7) + ((lane & 16) >> 1);
                const int ch = ks * 2 + ((lane >> 3) & 1);
                const uint32_t off = (uint32_t)(n * 128) + (((uint32_t)(ch ^ (n & 7))) << 4);
                uint32_t bh[4], bl[4];
                ldsm_x4(kh + off, bh);
                ldsm_x4(kl + off, bl);
                mma_bf16(sacc[2 * g + 0], qfh[ks], bh[0], bh[1]);
                mma_bf16(sacc[2 * g + 0], qfl, bh[0], bh[1]);
                mma_bf16(sacc[2 * g + 0], qfh[ks], bl[0], bl[1]);
                mma_bf16(sacc[2 * g + 1], qfh[ks], bh[2], bh[3]);
                mma_bf16(sacc[2 * g + 1], qfl, bh[2], bh[3]);
                mma_bf16(sacc[2 * g + 1], qfh[ks], bl[2], bl[3]);
            }
        }

        float mx0 = sacc[0][0], mx1 = sacc[0][2];
#pragma unroll
        for (int g = 0; g < 8; g++) {
            mx0 = fmaxf(mx0, fmaxf(sacc[g][0], sacc[g][1]));
            mx1 = fmaxf(mx1, fmaxf(sacc[g][2], sacc[g][3]));
        }
        mx0 = fmaxf(mx0, __shfl_xor_sync(0xffffffffu, mx0, 1));
        mx0 = fmaxf(mx0, __shfl_xor_sync(0xffffffffu, mx0, 2));
        mx1 = fmaxf(mx1, __shfl_xor_sync(0xffffffffu, mx1, 1));
        mx1 = fmaxf(mx1, __shfl_xor_sync(0xffffffffu, mx1, 2));
        const float mn0 = fmaxf(m0, mx0);
        const float mn1 = fmaxf(m1, mx1);
        const float a0 = fast_exp(m0 - mn0);
        const float a1 = fast_exp(m1 - mn1);
        m0 = mn0; m1 = mn1;
        float s0s = 0.f, s1s = 0.f;
#pragma unroll
        for (int g = 0; g < 8; g++) {
            sacc[g][0] = fast_exp(sacc[g][0] - mn0);
            sacc[g][1] = fast_exp(sacc[g][1] - mn0);
            sacc[g][2] = fast_exp(sacc[g][2] - mn1);
            sacc[g][3] = fast_exp(sacc[g][3] - mn1);
            s0s += sacc[g][0] + sacc[g][1];
            s1s += sacc[g][2] + sacc[g][3];
        }
        l0 = l0 * a0 + s0s;
        l1 = l1 * a1 + s1s;
#pragma unroll
        for (int g = 0; g < 8; g++) {
            oacc[g][0] *= a0; oacc[g][1] *= a0;
            oacc[g][2] *= a1; oacc[g][3] *= a1;
        }

#pragma unroll
        for (int ks = 0; ks < 4; ks++) {
            uint32_t ah[4], al[4];
            pack_split(sacc[2 * ks][0],     sacc[2 * ks][1],     ah[0], al[0]);
            pack_split(sacc[2 * ks][2],     sacc[2 * ks][3],     ah[1], al[1]);
            pack_split(sacc[2 * ks + 1][0], sacc[2 * ks + 1][1], ah[2], al[2]);
            pack_split(sacc[2 * ks + 1][2], sacc[2 * ks + 1][3], ah[3], al[3]);
            const int tile2 = lane >> 3;
            const int key = ks * 16 + (tile2 & 1) * 8 + (lane & 7);
#pragma unroll
            for (int g = 0; g < 4; g++) {
                const int c = g * 2 + (tile2 >> 1);
                const uint32_t off = (uint32_t)(key * 128) + (((uint32_t)(c ^ (key & 7))) << 4);
                uint32_t bh[4], bl[4];
                ldsm_x4t(vh + off, bh);
                ldsm_x4t(vl + off, bl);
                mma_bf16(oacc[2 * g + 0], ah, bh[0], bh[1]);
                mma_bf16(oacc[2 * g + 0], al, bh[0], bh[1]);
                mma_bf16(oacc[2 * g + 0], ah, bl[0], bl[1]);
                mma_bf16(oacc[2 * g + 1], ah, bh[2], bh[3]);
                mma_bf16(oacc[2 * g + 1], al, bh[2], bh[3]);
                mma_bf16(oacc[2 * g + 1], ah, bl[2], bl[3]);
            }
        }
        __syncthreads();
    }

    l0 += __shfl_xor_sync(0xffffffffu, l0, 1);
    l0 += __shfl_xor_sync(0xffffffffu, l0, 2);
    l1 += __shfl_xor_sync(0xffffffffu, l1, 1);
    l1 += __shfl_xor_sync(0xffffffffu, l1, 2);
    const float inv0 = 1.0f / l0;
    const float inv1 = 1.0f / l1;
    const int r0 = s0 + wid * 16 + (lane >> 2);
#pragma unroll
    for (int g = 0; g < 8; g++) {
        const int col = h * HD + g * 8 + (lane & 3) * 2;
        *(float2*)&Ofp[((size_t)(b * SQ) + r0) * DMODEL + col] =
            make_float2(__uint_as_float(rna_tf32(oacc[g][0] * inv0)),
                        __uint_as_float(rna_tf32(oacc[g][1] * inv0)));
        *(float2*)&Ofp[((size_t)(b * SQ) + r0 + 8) * DMODEL + col] =
            make_float2(__uint_as_float(rna_tf32(oacc[g][2] * inv1)),
                        __uint_as_float(rna_tf32(oacc[g][3] * inv1)));
    }
}

// ---------------------------------------------------------------------------
extern "C" void kernel_launch(void* const* d_in, const int* in_sizes, int n_in,
                              void* d_out, int out_size)
{
    const float* query = (const float*)d_in[0];
    const float* kv    = (const float*)d_in[1];
    const float* q_w   = (const float*)d_in[2];
    const float* q_b   = (const float*)d_in[3];
    const float* k_w   = (const float*)d_in[4];
    const float* k_b   = (const float*)d_in[5];
    const float* v_w   = (const float*)d_in[6];
    const float* v_b   = (const float*)d_in[7];
    const float* out_w = (const float*)d_in[8];
    const float* out_b = (const float*)d_in[9];
    float* out = (float*)d_out;

    float *qr, *kvr, *wqr, *wkr, *wvr, *wor, *ofp;
    __nv_bfloat16 *aqh, *aql, *akh, *akl, *avh, *avl;
    cudaGetSymbolAddress((void**)&qr,  g_qr);  cudaGetSymbolAddress((void**)&kvr, g_kvr);
    cudaGetSymbolAddress((void**)&wqr, g_wqr); cudaGetSymbolAddress((void**)&wkr, g_wkr);
    cudaGetSymbolAddress((void**)&wvr, g_wvr); cudaGetSymbolAddress((void**)&wor, g_wor);
    cudaGetSymbolAddress((void**)&ofp, g_ofp);
    cudaGetSymbolAddress((void**)&aqh, g_aqh); cudaGetSymbolAddress((void**)&aql, g_aql);
    cudaGetSymbolAddress((void**)&akh, g_akh); cudaGetSymbolAddress((void**)&akl, g_akl);
    cudaGetSymbolAddress((void**)&avh, g_avh); cudaGetSymbolAddress((void**)&avl, g_avl);

    // launch 0: rna-round all GEMM operands (weights + inputs)
    round_all<<<16384, 256>>>(q_w, k_w, v_w, out_w, query, kv,
                              wqr, wkr, wvr, wor, qr, kvr);

    // launch 1: merged tf32 Q/K/V projections (bf16 hi/lo epilogues)
    cudaFuncSetAttribute(mma_gemm_qkv, cudaFuncAttributeMaxDynamicSharedMemorySize, GEMM_SMEM);
    mma_gemm_qkv<<<dim3(8, 160), 256, GEMM_SMEM>>>(qr, kvr, wqr, wkr, wvr,
                                                   q_b, k_b, v_b,
                                                   aqh, aql, akh, akl, avh, avl);

    // launch 2: attention (bf16 3-term; rna fp32 output)
    cudaFuncSetAttribute(attn_mma, cudaFuncAttributeMaxDynamicSharedMemorySize, ATTN_SMEM);
    attn_mma<<<dim3(SQ / 128, NHEAD, NB), 256, ATTN_SMEM>>>(aqh, aql, akh, akl, avh, avl, ofp);

    // launch 3: output projection (tf32 single-pass, fp32 out)
    cudaFuncSetAttribute(mma_gemm_o, cudaFuncAttributeMaxDynamicSharedMemorySize, GEMM_SMEM);
    mma_gemm_o<<<dim3(8, 32), 256, GEMM_SMEM>>>(ofp, wor, out_b, out);
}